// round 3
// baseline (speedup 1.0000x reference)
#include <cuda_runtime.h>

#define NQ    20
#define NPART 10
#define NB    128          // blocks in sim kernel
#define WPB   8            // warps per block -> 1024 warp-columns total
#define TPB   256

typedef unsigned long long ull;

__device__ float g_partial[NB][1024];
__device__ float g_G2[8][1024];

// ---------------- packed f32x2 helpers ----------------
__device__ __forceinline__ ull pack2(float x, float y) {
    ull r; asm("mov.b64 %0, {%1, %2};" : "=l"(r) : "f"(x), "f"(y)); return r;
}
__device__ __forceinline__ void unpack2(ull v, float& x, float& y) {
    asm("mov.b64 {%0, %1}, %2;" : "=f"(x), "=f"(y) : "l"(v));
}
__device__ __forceinline__ ull swap2(ull v) {
    float x, y; unpack2(v, x, y); return pack2(y, x);
}
__device__ __forceinline__ ull mul2(ull a, ull b) {
    ull r; asm("mul.rn.f32x2 %0, %1, %2;" : "=l"(r) : "l"(a), "l"(b)); return r;
}
__device__ __forceinline__ ull fma2(ull a, ull b, ull c) {
    ull r; asm("fma.rn.f32x2 %0, %1, %2, %3;" : "=l"(r) : "l"(a), "l"(b), "l"(c)); return r;
}

__device__ __forceinline__ float2 cmul(float2 a, float2 b) {
    return make_float2(a.x * b.x - a.y * b.y, a.x * b.y + a.y * b.x);
}
__device__ __forceinline__ float2 cadd(float2 a, float2 b) {
    return make_float2(a.x + b.x, a.y + b.y);
}

// packed gate constants: G[0]=dup(V00.x) G[1]=(-V00.y,V00.y) G[2..3]=V01 G[4..5]=V10 G[6..7]=V11
__device__ __forceinline__ void load_gate(const float2* sV, int q, ull G[8]) {
    float2 V00 = sV[4 * q + 0], V01 = sV[4 * q + 1];
    float2 V10 = sV[4 * q + 2], V11 = sV[4 * q + 3];
    G[0] = pack2(V00.x, V00.x); G[1] = pack2(-V00.y, V00.y);
    G[2] = pack2(V01.x, V01.x); G[3] = pack2(-V01.y, V01.y);
    G[4] = pack2(V10.x, V10.x); G[5] = pack2(-V10.y, V10.y);
    G[6] = pack2(V11.x, V11.x); G[7] = pack2(-V11.y, V11.y);
}

// one 2x2 complex butterfly on packed amps, f32x2 pipes
__device__ __forceinline__ void bfly(ull& A0, ull& A1, const ull G[8]) {
    ull a0s = swap2(A0), a1s = swap2(A1);
    ull r0 = mul2(G[1], a0s);
    r0 = fma2(G[0], A0, r0);
    r0 = fma2(G[3], a1s, r0);
    r0 = fma2(G[2], A1, r0);
    ull r1 = mul2(G[5], a0s);
    r1 = fma2(G[4], A0, r1);
    r1 = fma2(G[7], a1s, r1);
    r1 = fma2(G[6], A1, r1);
    A0 = r0; A1 = r1;
}

// ---------------------------------------------------------------------------
// sim: per-block redundant prep; each warp owns one column l, synthesizes
// 1024 amps (32 packed/thread), runs 5 register stages, warp-local transpose
// through padded shared, 5 more register stages, then |amp|^2 block-reduce.
// ---------------------------------------------------------------------------
__global__ void __launch_bounds__(TPB) sim_kernel(const float* __restrict__ x,
                                                  const float* __restrict__ w) {
    extern __shared__ float2 dyn[];
    float2* sT1   = dyn;             // [1024]
    float2* sT2   = dyn + 1024;      // [1024]
    float2* stage = dyn + 2048;      // [WPB][1056]  (32x33 padded, per warp)

    __shared__ float2 sv[NQ][2];
    __shared__ int    sFB[NQ];
    __shared__ float2 sV[40];
    __shared__ int    sXHlo[32];

    const int tid  = threadIdx.x;
    const int warp = tid >> 5;
    const int lane = tid & 31;

    const float RS2  = 0.70710678118654752440f;   // 1/sqrt(2)
    const float WMUL = 0.63245553203367586640f;   // sqrt(2/5)

    if (tid < NQ) {
        const int q = tid;
        float xq = x[q];
        float th = atanf(xq);
        float c, s;
        sincosf(0.5f * th, &s, &c);
        float a = (c - s) * RS2;
        float b = (c + s) * RS2;
        float ph = 0.5f * atanf(xq * xq);
        float pc, ps;
        sincosf(ph, &ps, &pc);
        sv[q][0] = make_float2(a * pc, -a * ps);
        sv[q][1] = make_float2(b * pc,  b * ps);

        int y = 1 << tid;
        for (int qq = NQ - 1; qq >= 0; --qq) {
            int cb  = 19 - qq;
            int tb2 = 19 - ((qq + 2) % NQ);
            int tb1 = 19 - ((qq + 1) % NQ);
            if ((y >> cb) & 1) y ^= (1 << tb2);
            if ((y >> cb) & 1) y ^= (1 << tb1);
        }
        sFB[tid] = y;
    }

    if (tid < NPART) {
        const int q = tid;
        float w0 = w[3 * q + 0] * WMUL;
        float w1 = w[3 * q + 1] * WMUL;
        float w2 = w[3 * q + 2] * WMUL;
        float c0, s0, c1, s1, c2, s2;
        sincosf(0.5f * w0, &s0, &c0);
        sincosf(0.5f * w1, &s1, &c1);
        sincosf(0.5f * w2, &s2, &c2);
        float2 r00 = make_float2(c0, 0.f), r01 = make_float2(0.f, -s0);
        float2 d0  = make_float2(c1, -s1), d1  = make_float2(c1,  s1);
        float2 A00 = cmul(d0, r00), A01 = cmul(d0, r01);
        float2 A10 = cmul(d1, r01), A11 = cmul(d1, r00);
        float2 m = make_float2(0.f, -s2);
        sV[4 * q + 0] = cadd(make_float2(c2 * A00.x, c2 * A00.y), cmul(m, A10));
        sV[4 * q + 1] = cadd(make_float2(c2 * A01.x, c2 * A01.y), cmul(m, A11));
        sV[4 * q + 2] = cadd(cmul(m, A00), make_float2(c2 * A10.x, c2 * A10.y));
        sV[4 * q + 3] = cadd(cmul(m, A01), make_float2(c2 * A11.x, c2 * A11.y));
    }
    __syncthreads();

#pragma unroll
    for (int a = tid; a < 1024; a += TPB) {
        float2 p1 = make_float2(1.f, 0.f);
        float2 p2 = make_float2(1.f, 0.f);
#pragma unroll
        for (int q = 0; q < NPART; ++q)
            p1 = cmul(p1, sv[q][(a >> (9 - q)) & 1]);
#pragma unroll
        for (int q = NPART; q < NQ; ++q)
            p2 = cmul(p2, sv[q][(a >> (19 - q)) & 1]);
        sT1[a] = p1;
        sT2[a] = p2;
    }
    if (tid < 32) {
        int v = 0;
#pragma unroll
        for (int i = 0; i < 5; ++i)
            if ((tid >> i) & 1) v ^= sFB[10 + i];
        sXHlo[tid] = v;
    }
    __syncthreads();

    // ---- this warp's column
    const int l = blockIdx.x * WPB + warp;
    int xl = 0;
#pragma unroll
    for (int j = 0; j < 10; ++j)
        if ((l >> j) & 1) xl ^= sFB[j];
    int xhhi = 0;
#pragma unroll
    for (int p = 0; p < 5; ++p)
        if ((lane >> p) & 1) xhhi ^= sFB[15 + p];
    const int xbase = xhhi ^ xl;

    // synthesize 32 packed amps/thread: h = (lane<<5) | r
    ull a[32];
#pragma unroll
    for (int r = 0; r < 32; ++r) {
        int xx = xbase ^ sXHlo[r];
        float2 z = cmul(sT1[xx >> 10], sT2[xx & 1023]);
        a[r] = pack2(z.x, z.y);
    }

    // phase 1: 5 register stages on h bits 0..4 (gates q = 9..5)
#pragma unroll
    for (int b = 0; b < 5; ++b) {
        ull G[8];
        load_gate(sV, 9 - b, G);
#pragma unroll
        for (int g = 0; g < 16; ++g) {
            int lo = g & ((1 << b) - 1);
            int r0 = ((g >> b) << (b + 1)) | lo;
            int r1 = r0 | (1 << b);
            bfly(a[r0], a[r1], G);
        }
    }

    // warp-local 32x32 transpose through padded shared (stride 33)
    float2* ws = stage + warp * 1056;
#pragma unroll
    for (int r = 0; r < 32; ++r) {
        float zx, zy; unpack2(a[r], zx, zy);
        ws[lane * 33 + r] = make_float2(zx, zy);
    }
    __syncwarp();
#pragma unroll
    for (int j = 0; j < 32; ++j) {
        float2 z = ws[j * 33 + lane];
        a[j] = pack2(z.x, z.y);
    }
    __syncwarp();

    // phase 2: 5 register stages on h bits 5..9 (gates q = 4..0); h = (j<<5)|lane
#pragma unroll
    for (int p = 0; p < 5; ++p) {
        ull G[8];
        load_gate(sV, 4 - p, G);
#pragma unroll
        for (int g = 0; g < 16; ++g) {
            int lo = g & ((1 << p) - 1);
            int r0 = ((g >> p) << (p + 1)) | lo;
            int r1 = r0 | (1 << p);
            bfly(a[r0], a[r1], G);
        }
    }

    // |amp|^2 into the (reused) per-warp staging region as floats
    float* wp = (float*)ws;
#pragma unroll
    for (int j = 0; j < 32; ++j) {
        float zx, zy; unpack2(a[j], zx, zy);
        wp[j * 33 + lane] = zx * zx + zy * zy;   // h = j*32 + lane
    }
    __syncthreads();

    // deterministic block reduce over the 8 warps
#pragma unroll
    for (int h = tid; h < 1024; h += TPB) {
        const int j  = h >> 5;
        const int lp = h & 31;
        float s = 0.f;
#pragma unroll
        for (int ww = 0; ww < WPB; ++ww)
            s += ((float*)(stage + ww * 1056))[j * 33 + lp];
        g_partial[blockIdx.x][h] = s;
    }
}

// ---- two-stage deterministic reduction, vectorized ----
__global__ void reduceA_kernel() {
    const int g = blockIdx.x;          // 0..7
    const int c = threadIdx.x;         // 0..255 float4 columns
    const float4* P = (const float4*)g_partial;   // [128][256]
    float4 s = make_float4(0.f, 0.f, 0.f, 0.f);
#pragma unroll
    for (int i = 0; i < 16; ++i) {
        float4 v = P[(g * 16 + i) * 256 + c];
        s.x += v.x; s.y += v.y; s.z += v.z; s.w += v.w;
    }
    ((float4*)g_G2)[g * 256 + c] = s;
}

__global__ void reduceB_kernel(float* __restrict__ out) {
    const int c = threadIdx.x;         // 0..255
    const float4* G = (const float4*)g_G2;        // [8][256]
    float4 s = make_float4(0.f, 0.f, 0.f, 0.f);
#pragma unroll
    for (int g = 0; g < 8; ++g) {
        float4 v = G[g * 256 + c];
        s.x += v.x; s.y += v.y; s.z += v.z; s.w += v.w;
    }
    ((float4*)out)[c] = s;
}

extern "C" void kernel_launch(void* const* d_in, const int* in_sizes, int n_in,
                              void* d_out, int out_size) {
    const float* x = (const float*)d_in[0];   // (1, 20) float32
    const float* w = (const float*)d_in[1];   // (60,)  float32
    float* out = (float*)d_out;               // (1, 1024) float32

    const int dynsmem = 2048 * 8 + WPB * 1056 * 8;   // T1+T2 + staging (bytes)
    cudaFuncSetAttribute(sim_kernel, cudaFuncAttributeMaxDynamicSharedMemorySize, dynsmem);
    sim_kernel<<<NB, TPB, dynsmem>>>(x, w);
    reduceA_kernel<<<8, 256>>>();
    reduceB_kernel<<<1, 256>>>(out);
}

// round 4
// speedup vs baseline: 1.0189x; 1.0189x over previous
#include <cuda_runtime.h>

#define NQ    20
#define NPART 10
#define NB    128          // sim blocks
#define TPB   512          // 16 warps = 8 warp-pairs = 8 columns per block

typedef unsigned long long ull;

__device__ float g_partial[NB][1024];
__device__ float g_G2[32][1024];

// ---------------- packed f32x2 helpers ----------------
__device__ __forceinline__ ull pack2(float x, float y) {
    ull r; asm("mov.b64 %0, {%1, %2};" : "=l"(r) : "f"(x), "f"(y)); return r;
}
__device__ __forceinline__ void unpack2(ull v, float& x, float& y) {
    asm("mov.b64 {%0, %1}, %2;" : "=f"(x), "=f"(y) : "l"(v));
}
__device__ __forceinline__ ull swap2(ull v) {
    float x, y; unpack2(v, x, y); return pack2(y, x);
}
__device__ __forceinline__ ull mul2(ull a, ull b) {
    ull r; asm("mul.rn.f32x2 %0, %1, %2;" : "=l"(r) : "l"(a), "l"(b)); return r;
}
__device__ __forceinline__ ull fma2(ull a, ull b, ull c) {
    ull r; asm("fma.rn.f32x2 %0, %1, %2, %3;" : "=l"(r) : "l"(a), "l"(b), "l"(c)); return r;
}
__device__ __forceinline__ ull add2(ull a, ull b) {
    ull r; asm("add.rn.f32x2 %0, %1, %2;" : "=l"(r) : "l"(a), "l"(b)); return r;
}

__device__ __forceinline__ float2 cmul(float2 a, float2 b) {
    return make_float2(a.x * b.x - a.y * b.y, a.x * b.y + a.y * b.x);
}
__device__ __forceinline__ float2 cadd(float2 a, float2 b) {
    return make_float2(a.x + b.x, a.y + b.y);
}

// packed gate: G[0]=dup(V00.x) G[1]=(-V00.y,V00.y), then V01, V10, V11
__device__ __forceinline__ void load_gate(const float2* sV, int q, ull G[8]) {
    float2 V00 = sV[4 * q + 0], V01 = sV[4 * q + 1];
    float2 V10 = sV[4 * q + 2], V11 = sV[4 * q + 3];
    G[0] = pack2(V00.x, V00.x); G[1] = pack2(-V00.y, V00.y);
    G[2] = pack2(V01.x, V01.x); G[3] = pack2(-V01.y, V01.y);
    G[4] = pack2(V10.x, V10.x); G[5] = pack2(-V10.y, V10.y);
    G[6] = pack2(V11.x, V11.x); G[7] = pack2(-V11.y, V11.y);
}

// balanced 2x2 complex butterfly: two independent depth-2 chains + add
__device__ __forceinline__ void bfly(ull& A0, ull& A1, const ull G[8]) {
    ull as = swap2(A0), bs = swap2(A1);
    ull t0 = fma2(G[0], A0, mul2(G[1], as));
    ull u0 = fma2(G[2], A1, mul2(G[3], bs));
    ull t1 = fma2(G[4], A0, mul2(G[5], as));
    ull u1 = fma2(G[6], A1, mul2(G[7], bs));
    A0 = add2(t0, u0);
    A1 = add2(t1, u1);
}

// swizzled exchange address (bijection on 0..1023, conflict-friendly)
__device__ __forceinline__ int xaddr(int h) {
    int row = h >> 4, col = h & 15;
    return row * 16 + (col ^ (row & 15));
}

// ---------------------------------------------------------------------------
// sim: 128 blocks x 512 threads; each warp-PAIR owns one column l.
// 16 packed amps/thread: phase1 = 4 reg stages (h bits 0-3), pair-local
// shared exchange (re/im planes, swizzled), 2 shfl stages (bits 4-5),
// 4 reg stages (bits 6-9), |amp|^2, block reduce over 8 columns.
// ---------------------------------------------------------------------------
__global__ void __launch_bounds__(TPB) sim_kernel(const float* __restrict__ x,
                                                  const float* __restrict__ w) {
    extern __shared__ float dynf[];
    // overlay: tables live only until synthesis; staging used after.
    float2* sT1 = (float2*)dynf;            // [1024]
    float2* sT2 = (float2*)dynf + 1024;     // [1024]
    // staging: 8 columns x (re[1024], im[1024])
    // column c planes: dynf + c*2048 (re), + 1024 (im)

    __shared__ float2 sv[NQ][2];
    __shared__ int    sFB[NQ];
    __shared__ float2 sV[40];
    __shared__ int    sXR[16];

    const int tid  = threadIdx.x;
    const int warp = tid >> 5;
    const int lane = tid & 31;
    const int c    = warp >> 1;        // column slot 0..7
    const int wp   = warp & 1;         // warp-in-pair
    const int pl   = (wp << 5) | lane; // pair-lane 0..63

    const float RS2  = 0.70710678118654752440f;
    const float WMUL = 0.63245553203367586640f;

    if (tid < NQ) {
        const int q = tid;
        float xq = x[q];
        float th = atanf(xq);
        float cc, ss;
        sincosf(0.5f * th, &ss, &cc);
        float a = (cc - ss) * RS2;
        float b = (cc + ss) * RS2;
        float ph = 0.5f * atanf(xq * xq);
        float pc, ps;
        sincosf(ph, &ps, &pc);
        sv[q][0] = make_float2(a * pc, -a * ps);
        sv[q][1] = make_float2(b * pc,  b * ps);

        int y = 1 << tid;
        for (int qq = NQ - 1; qq >= 0; --qq) {
            int cb  = 19 - qq;
            int tb2 = 19 - ((qq + 2) % NQ);
            int tb1 = 19 - ((qq + 1) % NQ);
            if ((y >> cb) & 1) y ^= (1 << tb2);
            if ((y >> cb) & 1) y ^= (1 << tb1);
        }
        sFB[tid] = y;
    }

    if (tid < NPART) {
        const int q = tid;
        float w0 = w[3 * q + 0] * WMUL;
        float w1 = w[3 * q + 1] * WMUL;
        float w2 = w[3 * q + 2] * WMUL;
        float c0, s0, c1, s1, c2, s2;
        sincosf(0.5f * w0, &s0, &c0);
        sincosf(0.5f * w1, &s1, &c1);
        sincosf(0.5f * w2, &s2, &c2);
        float2 r00 = make_float2(c0, 0.f), r01 = make_float2(0.f, -s0);
        float2 d0  = make_float2(c1, -s1), d1  = make_float2(c1,  s1);
        float2 A00 = cmul(d0, r00), A01 = cmul(d0, r01);
        float2 A10 = cmul(d1, r01), A11 = cmul(d1, r00);
        float2 m = make_float2(0.f, -s2);
        sV[4 * q + 0] = cadd(make_float2(c2 * A00.x, c2 * A00.y), cmul(m, A10));
        sV[4 * q + 1] = cadd(make_float2(c2 * A01.x, c2 * A01.y), cmul(m, A11));
        sV[4 * q + 2] = cadd(cmul(m, A00), make_float2(c2 * A10.x, c2 * A10.y));
        sV[4 * q + 3] = cadd(cmul(m, A01), make_float2(c2 * A11.x, c2 * A11.y));
    }
    __syncthreads();

    // product tables (2 entries/thread)
#pragma unroll
    for (int a = tid; a < 1024; a += TPB) {
        float2 p1 = make_float2(1.f, 0.f);
        float2 p2 = make_float2(1.f, 0.f);
#pragma unroll
        for (int q = 0; q < NPART; ++q)
            p1 = cmul(p1, sv[q][(a >> (9 - q)) & 1]);
#pragma unroll
        for (int q = NPART; q < NQ; ++q)
            p2 = cmul(p2, sv[q][(a >> (19 - q)) & 1]);
        sT1[a] = p1;
        sT2[a] = p2;
    }
    if (tid < 16) {
        int v = 0;
#pragma unroll
        for (int i = 0; i < 4; ++i)
            if ((tid >> i) & 1) v ^= sFB[10 + i];
        sXR[tid] = v;
    }
    __syncthreads();

    // ---- this pair's column
    const int l = blockIdx.x * 8 + c;
    int xl = 0;
#pragma unroll
    for (int j = 0; j < 10; ++j)
        if ((l >> j) & 1) xl ^= sFB[j];
    int plx = 0;
#pragma unroll
    for (int p = 0; p < 6; ++p)
        if ((pl >> p) & 1) plx ^= sFB[14 + p];   // h bit 4+p -> global bit 14+p
    const int xbase = xl ^ plx;

    // synthesize 16 packed amps: h = (pl<<4) | r
    ull a[16];
#pragma unroll
    for (int r = 0; r < 16; ++r) {
        int xx = xbase ^ sXR[r];
        float2 z = cmul(sT1[xx >> 10], sT2[xx & 1023]);
        a[r] = pack2(z.x, z.y);
    }
    __syncthreads();   // ALL warps done reading tables -> staging may overwrite

    // phase 1: 4 register stages on h bits 0..3 (gates q = 9,8,7,6)
#pragma unroll
    for (int b = 0; b < 4; ++b) {
        ull G[8];
        load_gate(sV, 9 - b, G);
#pragma unroll
        for (int g = 0; g < 8; ++g) {
            int lo = g & ((1 << b) - 1);
            int r0 = ((g >> b) << (b + 1)) | lo;
            int r1 = r0 | (1 << b);
            bfly(a[r0], a[r1], G);
        }
    }

    // pair-local exchange through swizzled re/im planes
    float* sRe = dynf + c * 2048;
    float* sIm = sRe + 1024;
#pragma unroll
    for (int r = 0; r < 16; ++r) {
        float zx, zy; unpack2(a[r], zx, zy);
        int ad = xaddr((pl << 4) | r);
        sRe[ad] = zx;
        sIm[ad] = zy;
    }
    asm volatile("bar.sync %0, %1;" :: "r"(c + 1), "r"(64) : "memory");

    // new assignment: h = (r'<<6)|(lane1<<5)|(lane0<<4)|(wp<<3)|(lane4<<2)|(lane3<<1)|lane2
    const int base6 = ((lane & 1) << 4) | ((lane & 2) << 4) | (wp << 3)
                    | (((lane >> 4) & 1) << 2) | (((lane >> 3) & 1) << 1) | ((lane >> 2) & 1);
#pragma unroll
    for (int r = 0; r < 16; ++r) {
        int ad = xaddr((r << 6) | base6);
        a[r] = pack2(sRe[ad], sIm[ad]);
    }
    asm volatile("bar.sync %0, %1;" :: "r"(c + 1), "r"(64) : "memory");

    // 2 shfl stages: h bit4 <-> lane0 (gate q=5), h bit5 <-> lane1 (gate q=4)
#pragma unroll
    for (int p = 0; p < 2; ++p) {
        const int q = 5 - p;
        float2 V00 = sV[4 * q + 0], V01 = sV[4 * q + 1];
        float2 V10 = sV[4 * q + 2], V11 = sV[4 * q + 3];
        const int bitv = (lane >> p) & 1;
        const float2 Vs = bitv ? V11 : V00;
        const float2 Vo = bitv ? V10 : V01;
        ull GsR = pack2(Vs.x, Vs.x), GsI = pack2(-Vs.y, Vs.y);
        ull GoR = pack2(Vo.x, Vo.x), GoI = pack2(-Vo.y, Vo.y);
#pragma unroll
        for (int r = 0; r < 16; ++r) {
            ull o = __shfl_xor_sync(0xffffffffu, a[r], 1 << p);
            ull t = fma2(GsR, a[r], mul2(GsI, swap2(a[r])));
            ull u = fma2(GoR, o,    mul2(GoI, swap2(o)));
            a[r] = add2(t, u);
        }
    }

    // phase 2: 4 register stages on h bits 6..9 (gates q = 3,2,1,0)
#pragma unroll
    for (int p = 0; p < 4; ++p) {
        ull G[8];
        load_gate(sV, 3 - p, G);
#pragma unroll
        for (int g = 0; g < 8; ++g) {
            int lo = g & ((1 << p) - 1);
            int r0 = ((g >> p) << (p + 1)) | lo;
            int r1 = r0 | (1 << p);
            bfly(a[r0], a[r1], G);
        }
    }

    // |amp|^2 -> re plane at plain h
#pragma unroll
    for (int r = 0; r < 16; ++r) {
        float zx, zy; unpack2(a[r], zx, zy);
        sRe[(r << 6) | base6] = zx * zx + zy * zy;
    }
    __syncthreads();

    // block reduce over the 8 columns
#pragma unroll
    for (int h = tid; h < 1024; h += TPB) {
        float s = 0.f;
#pragma unroll
        for (int cc = 0; cc < 8; ++cc)
            s += dynf[cc * 2048 + h];
        g_partial[blockIdx.x][h] = s;
    }
}

// ---- two-stage deterministic reduction, float4 ----
__global__ void reduceA_kernel() {
    const int g = blockIdx.x;          // 0..31
    const int cidx = threadIdx.x;      // 0..255
    const float4* P = (const float4*)g_partial;   // [128][256]
    float4 s = make_float4(0.f, 0.f, 0.f, 0.f);
#pragma unroll
    for (int i = 0; i < 4; ++i) {
        float4 v = P[(g * 4 + i) * 256 + cidx];
        s.x += v.x; s.y += v.y; s.z += v.z; s.w += v.w;
    }
    ((float4*)g_G2)[g * 256 + cidx] = s;
}

__global__ void reduceB_kernel(float* __restrict__ out) {
    const int cidx = threadIdx.x;      // 0..255
    const float4* G = (const float4*)g_G2;        // [32][256]
    float4 s = make_float4(0.f, 0.f, 0.f, 0.f);
#pragma unroll
    for (int g = 0; g < 32; ++g) {
        float4 v = G[g * 256 + cidx];
        s.x += v.x; s.y += v.y; s.z += v.z; s.w += v.w;
    }
    ((float4*)out)[cidx] = s;
}

extern "C" void kernel_launch(void* const* d_in, const int* in_sizes, int n_in,
                              void* d_out, int out_size) {
    const float* x = (const float*)d_in[0];   // (1, 20) float32
    const float* w = (const float*)d_in[1];   // (60,)  float32
    float* out = (float*)d_out;               // (1, 1024) float32

    const int dynsmem = 8 * 2048 * 4;         // 64 KB (tables overlay staging)
    cudaFuncSetAttribute(sim_kernel, cudaFuncAttributeMaxDynamicSharedMemorySize, dynsmem);
    sim_kernel<<<NB, TPB, dynsmem>>>(x, w);
    reduceA_kernel<<<32, 256>>>();
    reduceB_kernel<<<1, 256>>>(out);
}